// round 11
// baseline (speedup 1.0000x reference)
#include <cuda_runtime.h>

#define DD     10000   // hypervector dimensions
#define TT     128     // time steps
#define CC     32      // channels
#define BB     4       // batch
#define NCLS   10
#define NWIN   125     // T - NGRAM + 1
#define TD     125     // d-tile per block (DD/TD = 80 exactly)
#define NTILES 80
#define NPAIR  (NTILES * BB)    // 320 (tile,b) pairs
#define TROWS  66               // t-rows per half-block (incl. 3-row halo overlap)

// Scratch (device globals — no allocation allowed; zero-initialized at load)
__device__ int      g_acc[NPAIR * 2 * 128];          // per-half per-col exact partials
__device__ unsigned g_pair[NPAIR];                   // per-pair arrival tickets
__device__ float    g_partial[NPAIR * NCLS];         // per-tile class partials
__device__ unsigned g_ticket2;                       // finisher counter

// ---------------------------------------------------------------------------
// Fused kernel, grid (NTILES, BB, 2), 512 threads = 16 warps.
// Half h = blockIdx.z owns t-rows [62h, 62h+66) and windows
// [63h, 63h + (63-h)). col = tid&127, q = tid>>7 splits rows/windows 4-way.
//  Pre  : pack per-thread timestamp sign bits (<=17 LDG, MLP-hoisted) and
//         preload <=3 classify weights per thread.
//  Setup: q==0,col<66 builds packed histogram for its t-row; q==1 packs the
//         column's 21 signal signs (int8 +-1, 6 words).
//  A    : dp4a (no global loads) -> row-major int8 samples tile [66 x 128].
//  B    : quarter of this half's windows per thread (int32, exact).
//  C    : pair combine via g_acc + ticket; SECOND block of each pair folds
//         +-classify_w (class split 3/3/3/1 x col-group), writes g_partial.
//  Tail : 320th finisher reduces tile partials in fixed order -> out.
// ---------------------------------------------------------------------------
__global__ __launch_bounds__(512) void k_fused(
    const float* __restrict__ x,
    const float* __restrict__ signals_w,
    const float* __restrict__ timestamps_w,
    const float* __restrict__ classify_w,
    float* __restrict__ out)
{
    __shared__ __align__(16) unsigned cnt_s[TROWS * 8]; // packed histograms
    __shared__ int sw_s[6][128];                        // packed signal signs
    __shared__ signed char ss[TROWS * 128];             // row-major samples
    __shared__ int   acc_s[4][128];                     // window-quarter partials
    __shared__ float wsum2[NCLS][4];                    // per-(class, col-group)
    __shared__ int   pair_flag, last_flag;

    const int tid  = threadIdx.x;
    const int col  = tid & 127;
    const int q    = tid >> 7;          // 0..3
    const int cg   = (tid >> 5) & 3;    // col-group 0..3
    const int tile = blockIdx.x;
    const int b    = blockIdx.y;
    const int h    = blockIdx.z;        // half 0/1
    const int d0   = tile * TD;
    const int th0  = h ? 62 : 0;        // first global t-row of this half
    const int w0   = h ? 63 : 0;        // first global window of this half
    const int wcnt = h ? 62 : 63;       // windows in this half
    const int rq0  = 17 * q;            // first local row of this thread
    const int rcnt = (q == 3) ? 15 : 17;

    int dp = d0 - 3 + col;              // roll halo; only tile 0 wraps
    if (dp < 0) dp += DD;

    // --- Pre: timestamp sign bits for this thread's rows (LDG latency here) ---
    unsigned tsbits = 0;
#pragma unroll
    for (int j = 0; j < 17; j++)
        if (j < rcnt)
            tsbits |= (__float_as_uint(timestamps_w[(th0 + rq0 + j) * DD + dp]) >> 31) << j;

    // --- Pre: classify weights. Class-group q owns classes 3q..min(3q+2,9) ---
    const int n0 = 3 * q;               // 0,3,6,9 ; sizes 3/3/3/1
    float cw[3];
#pragma unroll
    for (int j = 0; j < 3; j++) {
        const int n = n0 + j;
        cw[j] = (n < NCLS && col < TD) ? classify_w[n * DD + d0 + col] : 0.f;
    }

    if (q == 0 && col < TROWS) {
        // --- Histogram for local row col (packed: 21 levels, <=32 per byte) ---
        uint4 z = make_uint4(0u, 0u, 0u, 0u);
        *(uint4*)&cnt_s[col * 8]     = z;
        *(uint4*)&cnt_s[col * 8 + 4] = z;
        const float4* xp = (const float4*)(x + (b * TT + th0 + col) * CC);
#pragma unroll
        for (int c4 = 0; c4 < CC / 4; c4++) {
            float4 v4 = xp[c4];
            float vv[4] = {v4.x, v4.y, v4.z, v4.w};
#pragma unroll
            for (int j = 0; j < 4; j++) {
                float v = (vv[j] / 20.0f) * 20.0f;   // mirrors reference fp exactly
                int iv = __float2int_rn(v);          // round half-to-even == jnp.round
                iv = iv < 0 ? 0 : (iv > 20 ? 20 : iv);
                cnt_s[col * 8 + (iv >> 2)] += 1u << ((iv & 3) * 8);
            }
        }
    } else if (q == 1) {
        // --- Pack column col's 21 signal signs as int8 bytes (+1 / -1) ---
        unsigned sw[6] = {0u, 0u, 0u, 0u, 0u, 0u};
#pragma unroll
        for (int l = 0; l < 21; l++) {
            unsigned neg  = __float_as_uint(signals_w[l * DD + dp]) >> 31;
            unsigned byte = neg ? 0xFFu : 0x01u;
            sw[l >> 2] |= byte << ((l & 3) * 8);
        }
#pragma unroll
        for (int l = 0; l < 6; l++) sw_s[l][col] = (int)sw[l];
    }
    __syncthreads();

    const int sp0 = sw_s[0][col], sp1 = sw_s[1][col], sp2 = sw_s[2][col];
    const int sp3 = sw_s[3][col], sp4 = sw_s[4][col], sp5 = sw_s[5][col];

    // --- Phase A: this thread's rows, dp4a only, no global loads ---
#pragma unroll
    for (int j = 0; j < 17; j++) {
        if (j < rcnt) {
            const int lt = rq0 + j;
            uint4 ca = *(const uint4*)&cnt_s[lt * 8];       // broadcast LDS
            uint2 cb = *(const uint2*)&cnt_s[lt * 8 + 4];
            int a = 0;
            a = __dp4a((int)ca.x, sp0, a);
            a = __dp4a((int)ca.y, sp1, a);
            a = __dp4a((int)ca.z, sp2, a);
            a = __dp4a((int)ca.w, sp3, a);
            a = __dp4a((int)cb.x, sp4, a);
            a = __dp4a((int)cb.y, sp5, a);
            int v = ((tsbits >> j) & 1u) ? -a : a;          // |v| <= 32
            ss[lt * 128 + col] = (signed char)v;
        }
    }
    __syncthreads();

    // --- Phase B: this thread's quarter of this half's windows (exact) ---
    {
        const int jcnt = wcnt - 16 * q > 16 ? 16 : wcnt - 16 * q;  // 16/16/16/15|14
        int acc = 0;
        if (col < TD) {
#pragma unroll 4
            for (int j = 0; j < jcnt; j++) {
                const int li = (w0 - th0) + 16 * q + j;     // local first row of window
                int p0 = ss[(li + 0) * 128 + col + 0];
                int p1 = ss[(li + 1) * 128 + col + 1];
                int p2 = ss[(li + 2) * 128 + col + 2];
                int p3 = ss[(li + 3) * 128 + col + 3];
                acc += p0 * p1 * p2 * p3;
            }
        }
        acc_s[q][col] = acc;
    }
    __syncthreads();

    // --- Pair combine: publish this half's per-col sums; second block finishes ---
    const int pairid = b * NTILES + tile;
    const int own = acc_s[0][col] + acc_s[1][col] + acc_s[2][col] + acc_s[3][col];
    if (q == 0) g_acc[(pairid * 2 + h) * 128 + col] = own;
    __threadfence();
    __syncthreads();                    // all g_acc writes issued before ticket
    if (tid == 0) {
        unsigned tk = atomicAdd(&g_pair[pairid], 1u);
        pair_flag = (tk == 1u);
    }
    __syncthreads();
    if (!pair_flag) return;             // first arrival: done (uniform exit)

    if (tid == 0) g_pair[pairid] = 0u;  // reset for next graph replay
    __threadfence();                    // acquire other half's g_acc writes

    // --- Phase C (finisher): combined acc -> hard-quantize -> classify fold ---
    {
        const int other = g_acc[(pairid * 2 + (1 - h)) * 128 + col];
        const int acc = own + other;
        float val[3];
#pragma unroll
        for (int j = 0; j < 3; j++)
            val[j] = (acc > 0) ? cw[j] : -cw[j];   // padded/inactive lanes hold 0
#pragma unroll
        for (int j = 0; j < 3; j++) {
#pragma unroll
            for (int off = 16; off > 0; off >>= 1)
                val[j] += __shfl_down_sync(0xffffffffu, val[j], off);
        }
        if ((tid & 31) == 0) {
#pragma unroll
            for (int j = 0; j < 3; j++) {
                const int n = n0 + j;
                if (n < NCLS) wsum2[n][cg] = val[j];
            }
        }
    }
    __syncthreads();
    if (tid < NCLS) {
        float s = wsum2[tid][0] + wsum2[tid][1] + wsum2[tid][2] + wsum2[tid][3];
        g_partial[pairid * NCLS + tid] = s;
    }

    // --- Deterministic final reduction by the 320th finisher ---
    __threadfence();
    __syncthreads();
    if (tid == 0) {
        unsigned tk = atomicAdd(&g_ticket2, 1u);
        last_flag = (tk == NPAIR - 1);
    }
    __syncthreads();
    if (last_flag) {
        if (tid == 0) g_ticket2 = 0u;   // reset for next graph replay
        __threadfence();
        if (tid < BB * NCLS) {
            int bb = tid / NCLS, n = tid % NCLS;
            float s = 0.f;
            for (int t2 = 0; t2 < NTILES; t2++)
                s += g_partial[(bb * NTILES + t2) * NCLS + n];
            out[bb * NCLS + n] = s;
        }
    }
}

extern "C" void kernel_launch(void* const* d_in, const int* in_sizes, int n_in,
                              void* d_out, int out_size) {
    const float* x            = (const float*)d_in[0];  // [4,128,32]
    const float* signals_w    = (const float*)d_in[1];  // [21,10000]
    // d_in[2] = channels_w : dead bind in reference, intentionally unused
    const float* timestamps_w = (const float*)d_in[3];  // [128,10000]
    const float* classify_w   = (const float*)d_in[4];  // [10,10000]
    float* out = (float*)d_out;                         // [4,10] fp32

    k_fused<<<dim3(NTILES, BB, 2), 512>>>(x, signals_w, timestamps_w, classify_w, out);
}